// round 3
// baseline (speedup 1.0000x reference)
#include <cuda_runtime.h>

#define MAXN 100000
#define MAXE 3200000
#define MAXG 512

// ---------------- scratch (device globals; no allocation allowed) ----------
__device__ int g_deg[MAXN];
__device__ int g_start[MAXN];
__device__ int g_cursor[MAXN];
__device__ int g_csr[MAXE];
__device__ int g_bsum[512];
__device__ int g_boff[512];
__device__ __align__(16) float g_t[MAXN * 8];
__device__ __align__(16) float g_h2[MAXN * 8];
__device__ float g_as2[MAXN];
__device__ float g_ad2[MAXN];
__device__ __align__(16) float g_gsum[MAXG * 8];
__device__ float g_gcnt[MAXG];
__device__ float g_s1[8];
__device__ float g_d1[8];

__device__ __forceinline__ float lrelu(float z) { return z > 0.f ? z : 0.2f * z; }

// ---------------- zero scratch ----------------
__global__ void zero_all(int N, int G) {
    int i = blockIdx.x * blockDim.x + threadIdx.x;
    if (i < N) g_deg[i] = 0;
    if (i < G * 8) g_gsum[i] = 0.f;
    if (i < G) g_gcnt[i] = 0.f;
}

// ---------------- precompute s1[h], d1[h] ----------------
__global__ void precomp(const float* __restrict__ W1,
                        const float* __restrict__ as1,
                        const float* __restrict__ ad1) {
    int h = threadIdx.x;
    if (h >= 8) return;
    float s = 0.f, d = 0.f;
#pragma unroll
    for (int c = 0; c < 8; c++) {
        float w = W1[h * 8 + c];
        s += w * as1[h * 8 + c];
        d += w * ad1[h * 8 + c];
    }
    g_s1[h] = s;
    g_d1[h] = d;
}

// ---------------- CSR build: histogram ----------------
__global__ void hist_k(const int* __restrict__ ei, int E) {
    int i = blockIdx.x * blockDim.x + threadIdx.x;
    if (i >= E) return;
    atomicAdd(&g_deg[ei[E + i]], 1);
}

// ---------------- CSR build: 3-phase exclusive scan over deg ----------------
__global__ void scan1_k(int N) {  // per-block sums
    __shared__ int sh[256];
    int t = threadIdx.x;
    int i = blockIdx.x * 256 + t;
    sh[t] = (i < N) ? g_deg[i] : 0;
    __syncthreads();
#pragma unroll
    for (int s = 128; s > 0; s >>= 1) {
        if (t < s) sh[t] += sh[t + s];
        __syncthreads();
    }
    if (t == 0) g_bsum[blockIdx.x] = sh[0];
}

__global__ void scan2_k(int B) {  // exclusive scan of block sums (B <= 512)
    __shared__ int sh[512];
    int t = threadIdx.x;
    int v = (t < B) ? g_bsum[t] : 0;
    sh[t] = v;
    __syncthreads();
#pragma unroll
    for (int o = 1; o < 512; o <<= 1) {
        int a = (t >= o) ? sh[t - o] : 0;
        __syncthreads();
        sh[t] += a;
        __syncthreads();
    }
    if (t < B) g_boff[t] = sh[t] - v;
}

__global__ void scan3_k(int N) {  // in-block exclusive scan + block offset
    __shared__ int sh[256];
    int t = threadIdx.x;
    int i = blockIdx.x * 256 + t;
    int v = (i < N) ? g_deg[i] : 0;
    sh[t] = v;
    __syncthreads();
#pragma unroll
    for (int o = 1; o < 256; o <<= 1) {
        int a = (t >= o) ? sh[t - o] : 0;
        __syncthreads();
        sh[t] += a;
        __syncthreads();
    }
    if (i < N) {
        int ex = sh[t] - v + g_boff[blockIdx.x];
        g_start[i] = ex;
        g_cursor[i] = ex;
    }
}

// ---------------- CSR build: scatter src by dst ----------------
__global__ void scatter_k(const int* __restrict__ ei, int E) {
    int i = blockIdx.x * blockDim.x + threadIdx.x;
    if (i >= E) return;
    int d = ei[E + i];
    int pos = atomicAdd(&g_cursor[d], 1);
    g_csr[pos] = ei[i];
}

// ---------------- layer 1: warp-per-dst gather (no atomics) ----------------
// t[d,h] = (sum_s w*xs + w_self*xd) / (sum_s w + w_self)
__global__ void gather1(const float* __restrict__ x, int N) {
    int d = (blockIdx.x * blockDim.x + threadIdx.x) >> 5;
    int lane = threadIdx.x & 31;
    if (d >= N) return;
    float s1[8], d1[8];
#pragma unroll
    for (int h = 0; h < 8; h++) { s1[h] = g_s1[h]; d1[h] = g_d1[h]; }
    float xd = __ldg(x + d);
    int beg = g_start[d], deg = g_deg[d];
    float den[8] = {0, 0, 0, 0, 0, 0, 0, 0};
    float num[8] = {0, 0, 0, 0, 0, 0, 0, 0};
    for (int k = lane; k < deg; k += 32) {
        int s = __ldg(&g_csr[beg + k]);
        float xs = __ldg(x + s);
#pragma unroll
        for (int h = 0; h < 8; h++) {
            float z = lrelu(fmaf(xs, s1[h], xd * d1[h]));
            float w = __expf(z);
            den[h] += w;
            num[h] = fmaf(w, xs, num[h]);
        }
    }
#pragma unroll
    for (int o = 16; o > 0; o >>= 1) {
#pragma unroll
        for (int h = 0; h < 8; h++) {
            den[h] += __shfl_xor_sync(0xffffffffu, den[h], o);
            num[h] += __shfl_xor_sync(0xffffffffu, num[h], o);
        }
    }
    if (lane == 0) {
        float t[8];
#pragma unroll
        for (int h = 0; h < 8; h++) {
            float w = __expf(lrelu(xd * (s1[h] + d1[h])));  // self-loop
            t[h] = (num[h] + w * xd) / (den[h] + w + 1e-16f);
        }
        *(float4*)&g_t[d * 8]     = make_float4(t[0], t[1], t[2], t[3]);
        *(float4*)&g_t[d * 8 + 4] = make_float4(t[4], t[5], t[6], t[7]);
    }
}

// ---------------- node MLP: elu(t*W1+b1) @ W2, att dots ----------------
__global__ void node1(const float* __restrict__ W1, const float* __restrict__ b1,
                      const float* __restrict__ W2,
                      const float* __restrict__ as2w, const float* __restrict__ ad2w,
                      int N) {
    __shared__ float sW1[64], sb1[64], sW2[512], sas[8], sad[8];
    int t = threadIdx.x;
    if (t < 64) { sW1[t] = W1[t]; sb1[t] = b1[t]; }
    for (int k = t; k < 512; k += blockDim.x) sW2[k] = W2[k];
    if (t < 8) { sas[t] = as2w[t]; sad[t] = ad2w[t]; }
    __syncthreads();

    int n = blockIdx.x * blockDim.x + t;
    if (n >= N) return;
    float4 t0 = *(const float4*)&g_t[n * 8];
    float4 t1 = *(const float4*)&g_t[n * 8 + 4];
    float tv[8] = {t0.x, t0.y, t0.z, t0.w, t1.x, t1.y, t1.z, t1.w};
    float acc[8];
#pragma unroll
    for (int c = 0; c < 8; c++) acc[c] = 0.f;
#pragma unroll
    for (int k = 0; k < 64; k++) {
        float v = fmaf(tv[k >> 3], sW1[k], sb1[k]);
        v = v > 0.f ? v : (__expf(v) - 1.f);  // fast ELU
#pragma unroll
        for (int c = 0; c < 8; c++) acc[c] = fmaf(v, sW2[k * 8 + c], acc[c]);
    }
    float as = 0.f, ad = 0.f;
#pragma unroll
    for (int c = 0; c < 8; c++) {
        g_h2[n * 8 + c] = acc[c];
        as = fmaf(acc[c], sas[c], as);
        ad = fmaf(acc[c], sad[c], ad);
    }
    g_as2[n] = as;
    g_ad2[n] = ad;
}

// ---------------- layer 2: warp-per-dst gather + pooling epilogue ----------
__global__ void gather2(const int* __restrict__ batch, const float* __restrict__ b2,
                        int N) {
    int d = (blockIdx.x * blockDim.x + threadIdx.x) >> 5;
    int lane = threadIdx.x & 31;
    if (d >= N) return;
    float ad = g_ad2[d];
    int beg = g_start[d], deg = g_deg[d];
    float acc[8] = {0, 0, 0, 0, 0, 0, 0, 0};
    float den = 0.f;
    for (int k = lane; k < deg; k += 32) {
        int s = __ldg(&g_csr[beg + k]);
        float w = __expf(lrelu(__ldg(g_as2 + s) + ad));
        float4 a = __ldg((const float4*)&g_h2[s * 8]);
        float4 b = __ldg((const float4*)&g_h2[s * 8 + 4]);
        acc[0] = fmaf(w, a.x, acc[0]);
        acc[1] = fmaf(w, a.y, acc[1]);
        acc[2] = fmaf(w, a.z, acc[2]);
        acc[3] = fmaf(w, a.w, acc[3]);
        acc[4] = fmaf(w, b.x, acc[4]);
        acc[5] = fmaf(w, b.y, acc[5]);
        acc[6] = fmaf(w, b.z, acc[6]);
        acc[7] = fmaf(w, b.w, acc[7]);
        den += w;
    }
#pragma unroll
    for (int o = 16; o > 0; o >>= 1) {
#pragma unroll
        for (int c = 0; c < 8; c++) acc[c] += __shfl_xor_sync(0xffffffffu, acc[c], o);
        den += __shfl_xor_sync(0xffffffffu, den, o);
    }
    if (lane == 0) {
        float w = __expf(lrelu(g_as2[d] + ad));  // self-loop
        float inv = 1.f / (den + w + 1e-16f);
        float o[8];
#pragma unroll
        for (int c = 0; c < 8; c++)
            o[c] = fmaf(acc[c] + w * g_h2[d * 8 + c], inv, b2[c]);
        int b = batch[d];
        atomicAdd((float4*)&g_gsum[b * 8], make_float4(o[0], o[1], o[2], o[3]));
        atomicAdd((float4*)&g_gsum[b * 8 + 4], make_float4(o[4], o[5], o[6], o[7]));
        atomicAdd(&g_gcnt[b], 1.f);
    }
}

// ---------------- pooled -> linear -> log_softmax ----------------
__global__ void final_k(const float* __restrict__ lw, const float* __restrict__ lb,
                        float* __restrict__ out, int G) {
    int g = blockIdx.x * blockDim.x + threadIdx.x;
    if (g >= G) return;
    float inv = 1.f / fmaxf(g_gcnt[g], 1.f);
    float p[8];
#pragma unroll
    for (int c = 0; c < 8; c++) p[c] = g_gsum[g * 8 + c] * inv;
    float l[10];
    float m = -1e30f;
#pragma unroll
    for (int o = 0; o < 10; o++) {
        float a = lb[o];
#pragma unroll
        for (int c = 0; c < 8; c++) a = fmaf(p[c], lw[c * 10 + o], a);
        l[o] = a;
        m = fmaxf(m, a);
    }
    float s = 0.f;
#pragma unroll
    for (int o = 0; o < 10; o++) s += expf(l[o] - m);
    float lse = m + logf(s);
#pragma unroll
    for (int o = 0; o < 10; o++) out[g * 10 + o] = l[o] - lse;
}

// ---------------- launch ----------------
extern "C" void kernel_launch(void* const* d_in, const int* in_sizes, int n_in,
                              void* d_out, int out_size) {
    const float* x   = (const float*)d_in[0];
    const int*   ei  = (const int*)d_in[1];
    const int*   bat = (const int*)d_in[2];
    const float* W1  = (const float*)d_in[4];
    const float* as1 = (const float*)d_in[5];
    const float* ad1 = (const float*)d_in[6];
    const float* b1  = (const float*)d_in[7];
    const float* W2  = (const float*)d_in[8];
    const float* as2 = (const float*)d_in[9];
    const float* ad2 = (const float*)d_in[10];
    const float* b2  = (const float*)d_in[11];
    const float* lw  = (const float*)d_in[12];
    const float* lb  = (const float*)d_in[13];

    int N = in_sizes[0];
    int E = in_sizes[1] / 2;
    int G = out_size / 10;
    float* out = (float*)d_out;

    int B1 = (N + 255) / 256;  // <= 512 for N <= 131072

    zero_all<<<(N + 255) / 256, 256>>>(N, G);
    precomp<<<1, 8>>>(W1, as1, ad1);
    hist_k<<<(E + 255) / 256, 256>>>(ei, E);
    scan1_k<<<B1, 256>>>(N);
    scan2_k<<<1, 512>>>(B1);
    scan3_k<<<B1, 256>>>(N);
    scatter_k<<<(E + 255) / 256, 256>>>(ei, E);
    gather1<<<(N * 32 + 255) / 256, 256>>>(x, N);
    node1<<<(N + 255) / 256, 256>>>(W1, b1, W2, as2, ad2, N);
    gather2<<<(N * 32 + 255) / 256, 256>>>(bat, b2, N);
    final_k<<<(G + 127) / 128, 128>>>(lw, lb, out, G);
}